// round 3
// baseline (speedup 1.0000x reference)
#include <cuda_runtime.h>

// ---------------- problem dims ----------------
#define Bn 256
#define Sn 336
#define Fn 8
#define Hn 512
#define Pn 96

// ---------------- partition ----------------
#define GB   2                 // batch groups
#define GHN  64                // h-column groups
#define NBLK (GB * GHN)        // 128 blocks, 1 per SM
#define BT   128               // batches per block
#define CT   8                 // h-cols per block
#define NR   32                // gate rows per block (4 * CT)
#define KC   64                // k chunk
#define NCHUNK (Hn / KC)       // 8

#define WSTRIDE (Hn + 4)       // 516 (pad: 8 row-starts hit distinct banks)
#define HSTRIDE (BT + 4)       // 132
#define HBUF    (KC * HSTRIDE) // floats per h_sh buffer

#define SMEM_FLOATS (NR * WSTRIDE + 2 * HBUF + BT * Fn + NR + NR * Fn)
#define SMEM_BYTES  (SMEM_FLOATS * 4)

// ---------------- device scratch (allowed: __device__ globals) ----------------
__device__ float    g_h[2][Hn][Bn];   // ping-pong h state, stored [col][batch]
__device__ unsigned g_bar_count;      // zero-initialized
__device__ unsigned g_bar_gen;

// ---------------- helpers ----------------
__device__ __forceinline__ void cp_async16(void* dst_sh, const void* src) {
    unsigned d = (unsigned)__cvta_generic_to_shared(dst_sh);
    asm volatile("cp.async.ca.shared.global [%0], [%1], 16;\n" :: "r"(d), "l"(src));
}
__device__ __forceinline__ void cp_commit() {
    asm volatile("cp.async.commit_group;\n" ::: "memory");
}
template <int N>
__device__ __forceinline__ void cp_wait() {
    asm volatile("cp.async.wait_group %0;\n" :: "n"(N) : "memory");
}

__device__ __forceinline__ float sigf(float x) {
    return 1.0f / (1.0f + __expf(-x));
}
__device__ __forceinline__ float tanh_fast(float x) {
    // 2*sigmoid(2x)-1; saturates correctly for large |x|
    return 2.0f / (1.0f + __expf(-2.0f * x)) - 1.0f;
}

// grid-wide barrier; all NBLK blocks are co-resident (1 block/SM, 128 <= 148)
__device__ __forceinline__ void grid_barrier() {
    __syncthreads();
    if (threadIdx.x == 0) {
        __threadfence();
        unsigned gen = *((volatile unsigned*)&g_bar_gen);
        if (atomicAdd(&g_bar_count, 1u) == NBLK - 1) {
            atomicExch(&g_bar_count, 0u);
            __threadfence();
            *((volatile unsigned*)&g_bar_gen) = gen + 1u;
        } else {
            while (*((volatile unsigned*)&g_bar_gen) == gen) { }
        }
        __threadfence();
    }
    __syncthreads();
}

// ---------------- kernel ----------------
__global__ void __launch_bounds__(256, 1)
lstm_kernel(const float* __restrict__ x_enc,
            const float* __restrict__ enc_Wih,
            const float* __restrict__ enc_Whh,
            const float* __restrict__ enc_b,
            const float* __restrict__ dec_Wih,
            const float* __restrict__ dec_Whh,
            const float* __restrict__ dec_b,
            const float* __restrict__ lin_W,
            const float* __restrict__ lin_b,
            float* __restrict__ out)
{
    extern __shared__ float smem[];
    float* w_sh    = smem;                        // [NR][WSTRIDE]
    float* h_sh    = w_sh + NR * WSTRIDE;         // [2][KC][HSTRIDE]
    float* x_sh    = h_sh + 2 * HBUF;             // [BT][Fn]
    float* bias_sh = x_sh + BT * Fn;              // [NR]
    float* wih_sh  = bias_sh + NR;                // [NR][Fn] (enc) / [NR] (dec)

    const int tid     = threadIdx.x;
    const int bid     = blockIdx.x;
    const int gh      = bid % GHN;
    const int gbx     = bid / GHN;
    const int bstart  = gbx * BT;
    const int colbase = gh * CT;

    const int c   = tid & 7;    // col within group (0..7)
    const int bq  = tid >> 3;   // batch quad (0..31)
    const int bl0 = bq * 4;     // local batch base

    // ---- load encoder weight slice into SMEM ----
    {
        const int r    = tid >> 3;   // local row 0..31
        const int seg  = tid & 7;
        const int gate = r >> 3;
        const int cc   = r & 7;
        const float* src = enc_Whh + (size_t)(gate * Hn + colbase + cc) * Hn + seg * 64;
        float*       dst = w_sh + r * WSTRIDE + seg * 64;
        #pragma unroll
        for (int j = 0; j < 16; j++)
            ((float4*)dst)[j] = ((const float4*)src)[j];

        if (tid < NR) {
            const int g2 = tid >> 3, c2 = tid & 7;
            bias_sh[tid] = enc_b[g2 * Hn + colbase + c2];
            #pragma unroll
            for (int k = 0; k < Fn; k++)
                wih_sh[tid * Fn + k] = enc_Wih[(size_t)(g2 * Hn + colbase + c2) * Fn + k];
        }
    }

    // ---- per-launch re-init of global scratch (graph replays must be identical) ----
    {
        float* z = &g_h[1][0][0] + bid * ((Hn * Bn) / NBLK);
        for (int j = tid; j < (Hn * Bn) / NBLK; j += 256) z[j] = 0.0f;
        const int per  = (Bn * Pn + NBLK - 1) / NBLK;   // 192
        const int base = bid * per;
        for (int j = tid; j < per; j += 256)
            if (base + j < Bn * Pn) out[base + j] = 0.0f;
    }

    float creg[4] = {0.f, 0.f, 0.f, 0.f};
    const float lw = lin_W[colbase + c];
    const float lb = lin_b[0];

    grid_barrier();   // scratch zeroed + weights staged everywhere

    for (int s = 0; s < Sn + Pn; s++) {
        const bool enc = (s < Sn);
        const float* hprev = &g_h[(s + 1) & 1][0][0];   // [Hn][Bn]
        float*       hnext = &g_h[s & 1][0][0];

        // ---- encoder -> decoder weight swap (once) ----
        if (s == Sn) {
            __syncthreads();
            const int r    = tid >> 3;
            const int seg  = tid & 7;
            const int gate = r >> 3;
            const int cc   = r & 7;
            const float* src = dec_Whh + (size_t)(gate * Hn + colbase + cc) * Hn + seg * 64;
            float*       dst = w_sh + r * WSTRIDE + seg * 64;
            #pragma unroll
            for (int j = 0; j < 16; j++)
                ((float4*)dst)[j] = ((const float4*)src)[j];
            if (tid < NR) {
                const int g2 = tid >> 3, c2 = tid & 7;
                bias_sh[tid] = dec_b[g2 * Hn + colbase + c2];
                wih_sh[tid]  = dec_Wih[g2 * Hn + colbase + c2];   // (4H x 1)
            }
            __syncthreads();
        }

        // ---- init accumulators: bias + input term ----
        float acc[4][4];
        if (enc) {
            {   // stage x_t tile: 128 batches x 8 feats
                const int b = tid >> 1, part = tid & 1;
                const float4 v = *(const float4*)(x_enc +
                        ((size_t)(bstart + b) * Sn + s) * Fn + part * 4);
                *((float4*)&x_sh[b * Fn + part * 4]) = v;
            }
            __syncthreads();
            #pragma unroll
            for (int i = 0; i < 4; i++) {
                #pragma unroll
                for (int g2 = 0; g2 < 4; g2++) {
                    float a = bias_sh[g2 * 8 + c];
                    #pragma unroll
                    for (int k = 0; k < Fn; k++)
                        a = fmaf(x_sh[(bl0 + i) * Fn + k], wih_sh[(g2 * 8 + c) * Fn + k], a);
                    acc[i][g2] = a;
                }
            }
        } else {
            float xv[4];
            #pragma unroll
            for (int i = 0; i < 4; i++) {
                const int b = bstart + bl0 + i;
                xv[i] = (s == Sn) ? x_enc[((size_t)b * Sn + (Sn - 1)) * Fn + 3]
                                  : out[(size_t)b * Pn + (s - Sn - 1)];
            }
            #pragma unroll
            for (int i = 0; i < 4; i++)
                #pragma unroll
                for (int g2 = 0; g2 < 4; g2++)
                    acc[i][g2] = fmaf(xv[i], wih_sh[g2 * 8 + c], bias_sh[g2 * 8 + c]);
        }

        // ---- GEMM over K=512, cp.async double-buffered h chunks ----
        // stage chunk 0 into buffer 0
        {
            #pragma unroll
            for (int j = 0; j < 8; j++) {
                const int idx = j * 256 + tid;      // 2048 float4 per chunk
                const int row = idx >> 5;
                const int q   = idx & 31;
                cp_async16(h_sh + row * HSTRIDE + q * 4,
                           hprev + (size_t)row * Bn + bstart + q * 4);
            }
            cp_commit();
        }

        for (int ci = 0; ci < NCHUNK; ci++) {
            const int kc = ci * KC;
            __syncthreads();  // everyone done with the buffer we are about to overwrite
            if (ci + 1 < NCHUNK) {
                float* dst = h_sh + ((ci + 1) & 1) * HBUF;
                const float* srcb = hprev + (size_t)(kc + KC) * Bn + bstart;
                #pragma unroll
                for (int j = 0; j < 8; j++) {
                    const int idx = j * 256 + tid;
                    const int row = idx >> 5;
                    const int q   = idx & 31;
                    cp_async16(dst + row * HSTRIDE + q * 4, srcb + (size_t)row * Bn + q * 4);
                }
                cp_commit();
                cp_wait<1>();
            } else {
                cp_wait<0>();
            }
            __syncthreads();  // staged chunk visible to all

            const float* hS = h_sh + (ci & 1) * HBUF;
            #pragma unroll 4
            for (int k = 0; k < KC; k += 4) {
                const float4 h0 = *(const float4*)(hS + (k + 0) * HSTRIDE + bl0);
                const float4 h1 = *(const float4*)(hS + (k + 1) * HSTRIDE + bl0);
                const float4 h2 = *(const float4*)(hS + (k + 2) * HSTRIDE + bl0);
                const float4 h3 = *(const float4*)(hS + (k + 3) * HSTRIDE + bl0);
                #pragma unroll
                for (int g2 = 0; g2 < 4; g2++) {
                    const float4 wv = *(const float4*)(w_sh + (g2 * 8 + c) * WSTRIDE + kc + k);
                    acc[0][g2] += h0.x * wv.x + h1.x * wv.y + h2.x * wv.z + h3.x * wv.w;
                    acc[1][g2] += h0.y * wv.x + h1.y * wv.y + h2.y * wv.z + h3.y * wv.w;
                    acc[2][g2] += h0.z * wv.x + h1.z * wv.y + h2.z * wv.z + h3.z * wv.w;
                    acc[3][g2] += h0.w * wv.x + h1.w * wv.y + h2.w * wv.z + h3.w * wv.w;
                }
            }
        }

        // ---- activations, state update, h write ----
        float hnew[4];
        #pragma unroll
        for (int i = 0; i < 4; i++) {
            const float ig = sigf(acc[i][0]);
            const float fg = sigf(acc[i][1]);
            const float gg = tanh_fast(acc[i][2]);
            const float og = sigf(acc[i][3]);
            const float cn = fmaf(fg, creg[i], ig * gg);
            creg[i] = cn;
            hnew[i] = og * tanh_fast(cn);
            hnext[(size_t)(colbase + c) * Bn + (bstart + bl0 + i)] = hnew[i];
        }

        // ---- decoder output: y = h @ lin_W^T + lin_b (cross-block via atomics) ----
        if (!enc) {
            float py[4];
            #pragma unroll
            for (int i = 0; i < 4; i++) py[i] = hnew[i] * lw;
            #pragma unroll
            for (int off = 4; off >= 1; off >>= 1) {
                #pragma unroll
                for (int i = 0; i < 4; i++)
                    py[i] += __shfl_down_sync(0xffffffffu, py[i], off, 8);
            }
            if (c == 0) {
                const float add = (gh == 0) ? lb : 0.0f;
                #pragma unroll
                for (int i = 0; i < 4; i++)
                    atomicAdd(&out[(size_t)(bstart + bl0 + i) * Pn + (s - Sn)], py[i] + add);
            }
        }

        grid_barrier();
    }
}

// ---------------- launch ----------------
extern "C" void kernel_launch(void* const* d_in, const int* in_sizes, int n_in,
                              void* d_out, int out_size)
{
    const float* x_enc   = (const float*)d_in[0];
    const float* enc_Wih = (const float*)d_in[1];
    const float* enc_Whh = (const float*)d_in[2];
    const float* enc_b   = (const float*)d_in[3];
    const float* dec_Wih = (const float*)d_in[4];
    const float* dec_Whh = (const float*)d_in[5];
    const float* dec_b   = (const float*)d_in[6];
    const float* lin_W   = (const float*)d_in[7];
    const float* lin_b   = (const float*)d_in[8];
    float* out = (float*)d_out;

    cudaFuncSetAttribute(lstm_kernel,
                         cudaFuncAttributeMaxDynamicSharedMemorySize, SMEM_BYTES);

    lstm_kernel<<<NBLK, 256, SMEM_BYTES>>>(x_enc, enc_Wih, enc_Whh, enc_b,
                                           dec_Wih, dec_Whh, dec_b,
                                           lin_W, lin_b, out);
}